// round 12
// baseline (speedup 1.0000x reference)
#include <cuda_runtime.h>
#include <math.h>
#include <stdint.h>

// Problem constants
#define BSZ   32
#define SSEQ  512
#define HDIM  1024
#define G3H   3072                  // 3*H
#define MROWS (BSZ * SSEQ)          // 16384
#define HB    (BSZ * HDIM)          // 32768 floats per h buffer
#define RCTAS 128                   // persistent recurrent CTAs (<=148 SMs)

// ---------------------------------------------------------------------------
// Scratch (static device globals — no allocation at kernel_launch time)
// ---------------------------------------------------------------------------
// gi laid out [t][j][b]  (j in [0,3H)) so the step kernel reads it coalesced
__device__ float g_gi[(size_t)SSEQ * G3H * BSZ];     // 192 MB
// layer-0 output in standard [b][s][h] layout (GEMM-A layout for layer 1)
__device__ float g_y0[(size_t)MROWS * HDIM];         // 64 MB
// ping-pong hidden state, lane-packed layout: element (hidx, b) lives at
// ((hidx>>2)*32 + b)*4 + (hidx&3)   -> 16B vector at [kq*32 + b], kq = hidx/4
__device__ float g_h[2][HB];
// grid barrier counter (monotonic within one persistent-kernel launch)
__device__ unsigned g_rbar;

// ---------------------------------------------------------------------------
// f32x2 packed-FMA helpers (FFMA2 — exact fp32, 2x throughput; ptxas never
// auto-generates these from C++)
// ---------------------------------------------------------------------------
__device__ __forceinline__ void fma2(unsigned long long& d,
                                     unsigned long long a,
                                     unsigned long long b)
{
    asm("fma.rn.f32x2 %0, %1, %2, %3;" : "=l"(d) : "l"(a), "l"(b), "l"(d));
}
__device__ __forceinline__ unsigned long long pack2(float x)
{
    unsigned long long r;
    asm("mov.b64 %0, {%1, %1};" : "=l"(r) : "f"(x));
    return r;
}
__device__ __forceinline__ float2 unpack2(unsigned long long v)
{
    float2 f;
    asm("mov.b64 {%0, %1}, %2;" : "=f"(f.x), "=f"(f.y) : "l"(v));
    return f;
}

// ---------------------------------------------------------------------------
// GEMM: C[m][n] = sum_k A[m][k] * W[n][k] + bias[n]
// A row-major [M=16384, K=1024], W row-major [N=3072, K=1024]
// Epilogue scatters into gi[s][n][b], m = b*512 + s
// BM=BN=128, BK=16, 256 threads, 8x8 microtile via FFMA2, register prefetch.
// ---------------------------------------------------------------------------
#define BM 128
#define BN 128
#define BK 16
#define TM 8
#define TN 8

__global__ __launch_bounds__(256, 2)
void gemm_gi_kernel(const float* __restrict__ A,
                    const float* __restrict__ W,
                    const float* __restrict__ bias,
                    float* __restrict__ gi)
{
    const int K = HDIM;
    __shared__ float As[BK][BM];
    __shared__ float Bs[BK][BN];

    const int tid = threadIdx.x;
    const int tx = tid & 15;          // 0..15  -> n microtile
    const int ty = tid >> 4;          // 0..15  -> m microtile
    const int m0 = blockIdx.y * BM;
    const int n0 = blockIdx.x * BN;

    // global->smem loading indices: 512 float4 per operand tile, 2 per thread
    const int lrow = tid >> 2;            // 0..63
    const int lc4  = (tid & 3) * 4;       // 0,4,8,12

    const float* Ab = A + (size_t)(m0 + lrow) * K + lc4;
    const float* Wb = W + (size_t)(n0 + lrow) * K + lc4;

    float4 pa0 = *(const float4*)(Ab);
    float4 pa1 = *(const float4*)(Ab + (size_t)64 * K);
    float4 pb0 = *(const float4*)(Wb);
    float4 pb1 = *(const float4*)(Wb + (size_t)64 * K);

    // acc2[i][j2]: packed pair over (n = 2*j2, 2*j2+1)
    unsigned long long acc2[TM][TN / 2];
#pragma unroll
    for (int i = 0; i < TM; i++)
#pragma unroll
        for (int j = 0; j < TN / 2; j++) acc2[i][j] = 0ull;

    for (int k0 = 0; k0 < K; k0 += BK) {
        As[lc4 + 0][lrow] = pa0.x; As[lc4 + 1][lrow] = pa0.y;
        As[lc4 + 2][lrow] = pa0.z; As[lc4 + 3][lrow] = pa0.w;
        As[lc4 + 0][lrow + 64] = pa1.x; As[lc4 + 1][lrow + 64] = pa1.y;
        As[lc4 + 2][lrow + 64] = pa1.z; As[lc4 + 3][lrow + 64] = pa1.w;
        Bs[lc4 + 0][lrow] = pb0.x; Bs[lc4 + 1][lrow] = pb0.y;
        Bs[lc4 + 2][lrow] = pb0.z; Bs[lc4 + 3][lrow] = pb0.w;
        Bs[lc4 + 0][lrow + 64] = pb1.x; Bs[lc4 + 1][lrow + 64] = pb1.y;
        Bs[lc4 + 2][lrow + 64] = pb1.z; Bs[lc4 + 3][lrow + 64] = pb1.w;
        __syncthreads();

        if (k0 + BK < K) {
            pa0 = *(const float4*)(Ab + k0 + BK);
            pa1 = *(const float4*)(Ab + (size_t)64 * K + k0 + BK);
            pb0 = *(const float4*)(Wb + k0 + BK);
            pb1 = *(const float4*)(Wb + (size_t)64 * K + k0 + BK);
        }

#pragma unroll
        for (int kk = 0; kk < BK; kk++) {
            float4 a0 = *(const float4*)&As[kk][ty * TM];
            float4 a1 = *(const float4*)&As[kk][ty * TM + 4];
            // b as packed pairs: (b0,b1),(b2,b3),(b4,b5),(b6,b7)
            ulonglong2 bl0 = *(const ulonglong2*)&Bs[kk][tx * TN];
            ulonglong2 bl1 = *(const ulonglong2*)&Bs[kk][tx * TN + 4];
            float ar[TM] = {a0.x, a0.y, a0.z, a0.w, a1.x, a1.y, a1.z, a1.w};
#pragma unroll
            for (int i = 0; i < TM; i++) {
                const unsigned long long aa = pack2(ar[i]);
                fma2(acc2[i][0], aa, bl0.x);
                fma2(acc2[i][1], aa, bl0.y);
                fma2(acc2[i][2], aa, bl1.x);
                fma2(acc2[i][3], aa, bl1.y);
            }
        }
        __syncthreads();
    }

    // Epilogue: add bias, scatter to gi[t][j][b]
#pragma unroll
    for (int i = 0; i < TM; i++) {
        const int m = m0 + ty * TM + i;
        const int b = m >> 9;           // m / 512
        const int s = m & 511;          // m % 512
#pragma unroll
        for (int j2 = 0; j2 < TN / 2; j2++) {
            const float2 v = unpack2(acc2[i][j2]);
            const int n = n0 + tx * TN + 2 * j2;
            gi[((size_t)s * G3H + n) * BSZ + b]     = v.x + bias[n];
            gi[((size_t)s * G3H + n + 1) * BSZ + b] = v.y + bias[n + 1];
        }
    }
}

// ---------------------------------------------------------------------------
// Persistent GRU recurrence: whole sequence in ONE launch.
// 128 CTAs x 256 threads; CTA owns 8 hidden units (24 gate rows).
// W_hh slice (96 KB) lives in smem for the entire sequence.
// Per step: warp w covers k-chunk [w*128, w*128+128); lanes = batch.
// All 24 rows register-blocked -> h read exactly once per CTA per step.
// Cross-warp k-reduction via smem, finalize by (hloc, b) threads, then a
// release/acquire grid barrier on a monotonic counter.
// ---------------------------------------------------------------------------
__global__ __launch_bounds__(256)
void gru_seq_kernel(const float* __restrict__ Whh,   // [3H, H] row-major
                    const float* __restrict__ bhh,   // [3H]
                    const float* __restrict__ gi,    // [S][3H][B]
                    float* __restrict__ hbuf,        // 2*HB ping-pong (buf0 zeroed)
                    float* __restrict__ y_out)       // [B][S][H]
{
    extern __shared__ float smem[];
    float* sw   = smem;                    // [24][1024]  = 96 KB
    float* sred = smem + 24 * HDIM;        // [8][24][32] = 24 KB

    const int tid  = threadIdx.x;
    const int lane = tid & 31;             // batch b
    const int w    = tid >> 5;             // warp 0..7 (k-split / finalize hloc)
    const int bx   = blockIdx.x;

    // Load this CTA's 24 W_hh rows into smem (once for the whole sequence).
    // row r = g*8 + hl  ->  global row g*H + bx*8 + hl
    for (int i = tid; i < 24 * (HDIM / 4); i += 256) {
        const int r  = i >> 8;                 // /256 float4 per row
        const int c4 = (i & 255) * 4;
        const int g = r >> 3, hl = r & 7;
        const float4 v = *(const float4*)&Whh[((size_t)g * HDIM + bx * 8 + hl) * HDIM + c4];
        *(float4*)&sw[(size_t)r * HDIM + c4] = v;
    }
    __syncthreads();

    const int hidx_f = bx * 8 + w;                               // finalize hidx
    const int pk_f   = ((hidx_f >> 2) * 32 + lane) * 4 + (hidx_f & 3);
    const float bias_r = bhh[hidx_f];
    const float bias_z = bhh[HDIM + hidx_f];
    const float bias_n = bhh[2 * HDIM + hidx_f];

    int cur = 0;
    for (int t = 0; t < SSEQ; ++t) {
        const float* h_in  = hbuf + (size_t)cur * HB;
        float*       h_out = hbuf + (size_t)(1 - cur) * HB;
        const ulonglong2* __restrict__ h2 = (const ulonglong2*)h_in;

        unsigned long long acc[24];
#pragma unroll
        for (int r = 0; r < 24; ++r) acc[r] = 0ull;

        const int kq0 = w * 32;
        ulonglong2 hv = h2[kq0 * 32 + lane];           // prefetch
        for (int kq = kq0; kq < kq0 + 32; ++kq) {
            const ulonglong2 hcur = hv;
            if (kq + 1 < kq0 + 32) hv = h2[(kq + 1) * 32 + lane];
            const float* wp = sw + 4 * kq;
#pragma unroll
            for (int r = 0; r < 24; ++r) {
                const ulonglong2 wv = *(const ulonglong2*)(wp + (size_t)r * HDIM);
                fma2(acc[r], wv.x, hcur.x);
                fma2(acc[r], wv.y, hcur.y);
            }
        }
#pragma unroll
        for (int r = 0; r < 24; ++r) {
            const float2 f = unpack2(acc[r]);
            sred[((size_t)w * 24 + r) * 32 + lane] = f.x + f.y;
        }
        __syncthreads();

        // ---- finalize: thread (hloc=w, b=lane) produces h[hidx_f][b] ----
        {
            float gr = bias_r, gz = bias_z, gn = bias_n;
#pragma unroll
            for (int ww = 0; ww < 8; ++ww) {
                gr += sred[((size_t)ww * 24 + 0 * 8 + w) * 32 + lane];
                gz += sred[((size_t)ww * 24 + 1 * 8 + w) * 32 + lane];
                gn += sred[((size_t)ww * 24 + 2 * 8 + w) * 32 + lane];
            }
            const float* git = gi + (size_t)t * G3H * BSZ;
            const float ir  = git[(size_t)hidx_f * BSZ + lane];
            const float iz  = git[(size_t)(HDIM + hidx_f) * BSZ + lane];
            const float inn = git[(size_t)(2 * HDIM + hidx_f) * BSZ + lane];

            const float r_ = 1.0f / (1.0f + expf(-(ir + gr)));
            const float z_ = 1.0f / (1.0f + expf(-(iz + gz)));
            const float n_ = tanhf(inn + r_ * gn);
            const float hprev = h_in[pk_f];
            const float hn = (1.0f - z_) * n_ + z_ * hprev;

            h_out[pk_f] = hn;
            y_out[((size_t)lane * SSEQ + t) * HDIM + hidx_f] = hn;
        }

        __syncthreads();                       // all stores program-ordered before arrive
        if (t != SSEQ - 1) {
            if (tid == 0) {
                const unsigned tgt = (unsigned)(t + 1) * RCTAS;
                unsigned* bar = &g_rbar;
                asm volatile("red.release.gpu.add.u32 [%0], %1;"
                             :: "l"(bar), "r"(1u) : "memory");
                unsigned v;
                for (;;) {
                    asm volatile("ld.acquire.gpu.u32 %0, [%1];"
                                 : "=r"(v) : "l"(bar) : "memory");
                    if (v >= tgt) break;
                    __nanosleep(32);
                }
            }
            __syncthreads();
        }
        cur ^= 1;
    }
}

// ---------------------------------------------------------------------------
__global__ void zero_h_kernel(float* __restrict__ h)
{
    const int i = blockIdx.x * 256 + threadIdx.x;
    if (i < HB) h[i] = 0.0f;
    if (i == 0) g_rbar = 0u;        // reset grid-barrier counter (deterministic replays)
}

// h_n[0] = y0[:, S-1, :], h_n[1] = y1[:, S-1, :]
__global__ void copy_hn_kernel(const float* __restrict__ y0,
                               const float* __restrict__ y1,
                               float* __restrict__ outhn)
{
    const int i = blockIdx.x * 256 + threadIdx.x;   // 0 .. 2*B*H-1
    if (i >= 2 * HB) return;
    const int half = HB;
    if (i < half) {
        const int b = i >> 10, h = i & 1023;
        outhn[i] = y0[((size_t)b * SSEQ + (SSEQ - 1)) * HDIM + h];
    } else {
        const int j = i - half;
        const int b = j >> 10, h = j & 1023;
        outhn[i] = y1[((size_t)b * SSEQ + (SSEQ - 1)) * HDIM + h];
    }
}

// ---------------------------------------------------------------------------
extern "C" void kernel_launch(void* const* d_in, const int* in_sizes, int n_in,
                              void* d_out, int out_size)
{
    const float* x    = (const float*)d_in[0];
    const float* Wih0 = (const float*)d_in[1];
    const float* bih0 = (const float*)d_in[2];
    const float* Whh0 = (const float*)d_in[3];
    const float* bhh0 = (const float*)d_in[4];
    const float* Wih1 = (const float*)d_in[5];
    const float* bih1 = (const float*)d_in[6];
    const float* Whh1 = (const float*)d_in[7];
    const float* bhh1 = (const float*)d_in[8];
    float* out = (float*)d_out;

    float* gi;  cudaGetSymbolAddress((void**)&gi,  g_gi);
    float* y0;  cudaGetSymbolAddress((void**)&y0,  g_y0);
    float* hb;  cudaGetSymbolAddress((void**)&hb,  g_h);

    const int SMEM_REC = (24 * HDIM + 8 * 24 * 32) * (int)sizeof(float);  // 120 KB
    static int smem_set = 0;
    if (!smem_set) {
        cudaFuncSetAttribute(gru_seq_kernel,
                             cudaFuncAttributeMaxDynamicSharedMemorySize, SMEM_REC);
        smem_set = 1;
    }

    const dim3 gemm_grid(G3H / BN, MROWS / BM);   // (24, 128)

    // ---- Layer 0 ----
    gemm_gi_kernel<<<gemm_grid, 256>>>(x, Wih0, bih0, gi);
    zero_h_kernel<<<(HB + 255) / 256, 256>>>(hb);
    gru_seq_kernel<<<RCTAS, 256, SMEM_REC>>>(Whh0, bhh0, gi, hb, y0);

    // ---- Layer 1 ----
    gemm_gi_kernel<<<gemm_grid, 256>>>(y0, Wih1, bih1, gi);
    zero_h_kernel<<<(HB + 255) / 256, 256>>>(hb);
    gru_seq_kernel<<<RCTAS, 256, SMEM_REC>>>(Whh1, bhh1, gi, hb, out);

    // ---- h_n tail (only if the harness output includes it) ----
    const long long need = (long long)MROWS * HDIM + 2LL * HB;
    if ((long long)out_size >= need) {
        copy_hn_kernel<<<(2 * HB + 255) / 256, 256>>>(y0, out, out + (size_t)MROWS * HDIM);
    }
}

// round 13
// speedup vs baseline: 1.3037x; 1.3037x over previous
#include <cuda_runtime.h>
#include <math.h>
#include <stdint.h>

// Problem constants
#define BSZ   32
#define SSEQ  512
#define HDIM  1024
#define G3H   3072                  // 3*H
#define MROWS (BSZ * SSEQ)          // 16384
#define HB    (BSZ * HDIM)          // 32768 floats per h buffer
#define RCTAS 128                   // persistent recurrent CTAs (<=148 SMs)

// ---------------------------------------------------------------------------
// Scratch (static device globals — no allocation at kernel_launch time)
// ---------------------------------------------------------------------------
__device__ float g_gi[(size_t)SSEQ * G3H * BSZ];     // [t][j][b]  192 MB
__device__ float g_y0[(size_t)MROWS * HDIM];         // [b][s][h]   64 MB
// ping-pong hidden state, lane-packed: (hidx,b) at ((hidx>>2)*32+b)*4+(hidx&3)
__device__ __align__(16) float g_h[2][HB];
__device__ unsigned g_rbar;                          // grid-barrier counter

// ---------------------------------------------------------------------------
// f32x2 packed-FMA helpers (FFMA2 — exact fp32, 2x throughput)
// ---------------------------------------------------------------------------
__device__ __forceinline__ void fma2(unsigned long long& d,
                                     unsigned long long a,
                                     unsigned long long b)
{
    asm("fma.rn.f32x2 %0, %1, %2, %3;" : "=l"(d) : "l"(a), "l"(b), "l"(d));
}
__device__ __forceinline__ unsigned long long pack2(float x)
{
    unsigned long long r;
    asm("mov.b64 %0, {%1, %1};" : "=l"(r) : "f"(x));
    return r;
}
__device__ __forceinline__ float2 unpack2(unsigned long long v)
{
    float2 f;
    asm("mov.b64 {%0, %1}, %2;" : "=f"(f.x), "=f"(f.y) : "l"(v));
    return f;
}

// ---------------------------------------------------------------------------
// GEMM: C[m][n] = sum_k A[m][k] * W[n][k] + bias[n]
// A row-major [16384,1024], W row-major [3072,1024]
// Double-buffered smem (2-stage): LDG(next) -> compute(cur) -> STS(next) -> sync
// Epilogue scatters into gi[s][n][b], m = b*512 + s
// ---------------------------------------------------------------------------
#define BM 128
#define BN 128
#define BK 16
#define TM 8
#define TN 8

__global__ __launch_bounds__(256, 2)
void gemm_gi_kernel(const float* __restrict__ A,
                    const float* __restrict__ W,
                    const float* __restrict__ bias,
                    float* __restrict__ gi)
{
    __shared__ float As[2][BK][BM];   // 16 KB
    __shared__ float Bs[2][BK][BN];   // 16 KB

    const int tid = threadIdx.x;
    const int tx = tid & 15;          // n microtile
    const int ty = tid >> 4;          // m microtile
    const int m0 = blockIdx.y * BM;
    const int n0 = blockIdx.x * BN;

    const int lrow = tid >> 2;            // 0..63
    const int lc4  = (tid & 3) * 4;       // 0,4,8,12

    const float* Ab = A + (size_t)(m0 + lrow) * HDIM + lc4;
    const float* Wb = W + (size_t)(n0 + lrow) * HDIM + lc4;

    float4 pa0 = *(const float4*)(Ab);
    float4 pa1 = *(const float4*)(Ab + (size_t)64 * HDIM);
    float4 pb0 = *(const float4*)(Wb);
    float4 pb1 = *(const float4*)(Wb + (size_t)64 * HDIM);

    unsigned long long acc2[TM][TN / 2];
#pragma unroll
    for (int i = 0; i < TM; i++)
#pragma unroll
        for (int j = 0; j < TN / 2; j++) acc2[i][j] = 0ull;

    // stage tile 0 into buffer 0
    {
        As[0][lc4 + 0][lrow] = pa0.x; As[0][lc4 + 1][lrow] = pa0.y;
        As[0][lc4 + 2][lrow] = pa0.z; As[0][lc4 + 3][lrow] = pa0.w;
        As[0][lc4 + 0][lrow + 64] = pa1.x; As[0][lc4 + 1][lrow + 64] = pa1.y;
        As[0][lc4 + 2][lrow + 64] = pa1.z; As[0][lc4 + 3][lrow + 64] = pa1.w;
        Bs[0][lc4 + 0][lrow] = pb0.x; Bs[0][lc4 + 1][lrow] = pb0.y;
        Bs[0][lc4 + 2][lrow] = pb0.z; Bs[0][lc4 + 3][lrow] = pb0.w;
        Bs[0][lc4 + 0][lrow + 64] = pb1.x; Bs[0][lc4 + 1][lrow + 64] = pb1.y;
        Bs[0][lc4 + 2][lrow + 64] = pb1.z; Bs[0][lc4 + 3][lrow + 64] = pb1.w;
    }
    __syncthreads();

    int buf = 0;
    for (int k0 = 0; k0 < HDIM; k0 += BK) {
        const bool nxt = (k0 + BK < HDIM);
        if (nxt) {
            pa0 = *(const float4*)(Ab + k0 + BK);
            pa1 = *(const float4*)(Ab + (size_t)64 * HDIM + k0 + BK);
            pb0 = *(const float4*)(Wb + k0 + BK);
            pb1 = *(const float4*)(Wb + (size_t)64 * HDIM + k0 + BK);
        }

#pragma unroll
        for (int kk = 0; kk < BK; kk++) {
            float4 a0 = *(const float4*)&As[buf][kk][ty * TM];
            float4 a1 = *(const float4*)&As[buf][kk][ty * TM + 4];
            ulonglong2 bl0 = *(const ulonglong2*)&Bs[buf][kk][tx * TN];
            ulonglong2 bl1 = *(const ulonglong2*)&Bs[buf][kk][tx * TN + 4];
            float ar[TM] = {a0.x, a0.y, a0.z, a0.w, a1.x, a1.y, a1.z, a1.w};
#pragma unroll
            for (int i = 0; i < TM; i++) {
                const unsigned long long aa = pack2(ar[i]);
                fma2(acc2[i][0], aa, bl0.x);
                fma2(acc2[i][1], aa, bl0.y);
                fma2(acc2[i][2], aa, bl1.x);
                fma2(acc2[i][3], aa, bl1.y);
            }
        }

        if (nxt) {
            const int nb = buf ^ 1;
            As[nb][lc4 + 0][lrow] = pa0.x; As[nb][lc4 + 1][lrow] = pa0.y;
            As[nb][lc4 + 2][lrow] = pa0.z; As[nb][lc4 + 3][lrow] = pa0.w;
            As[nb][lc4 + 0][lrow + 64] = pa1.x; As[nb][lc4 + 1][lrow + 64] = pa1.y;
            As[nb][lc4 + 2][lrow + 64] = pa1.z; As[nb][lc4 + 3][lrow + 64] = pa1.w;
            Bs[nb][lc4 + 0][lrow] = pb0.x; Bs[nb][lc4 + 1][lrow] = pb0.y;
            Bs[nb][lc4 + 2][lrow] = pb0.z; Bs[nb][lc4 + 3][lrow] = pb0.w;
            Bs[nb][lc4 + 0][lrow + 64] = pb1.x; Bs[nb][lc4 + 1][lrow + 64] = pb1.y;
            Bs[nb][lc4 + 2][lrow + 64] = pb1.z; Bs[nb][lc4 + 3][lrow + 64] = pb1.w;
            __syncthreads();
            buf = nb;
        }
    }

    // Epilogue: add bias, scatter to gi[t][j][b]
#pragma unroll
    for (int i = 0; i < TM; i++) {
        const int m = m0 + ty * TM + i;
        const int b = m >> 9;           // m / 512
        const int s = m & 511;          // m % 512
#pragma unroll
        for (int j2 = 0; j2 < TN / 2; j2++) {
            const float2 v = unpack2(acc2[i][j2]);
            const int n = n0 + tx * TN + 2 * j2;
            gi[((size_t)s * G3H + n) * BSZ + b]     = v.x + bias[n];
            gi[((size_t)s * G3H + n + 1) * BSZ + b] = v.y + bias[n + 1];
        }
    }
}

// ---------------------------------------------------------------------------
// Persistent GRU recurrence: whole sequence in ONE launch.
// 128 CTAs x 512 threads (16 warps). CTA owns 8 hidden units (24 gate rows).
// W_hh slice (96 KB) resident in smem for the entire sequence.
// Warp w covers k-chunk [w*64, w*64+64); lanes = batch; h read once per CTA.
// gi / h_prev prefetched at step top (hidden behind ~6K cyc of FFMA2).
// Cross-warp k-reduction via smem; coalesced y write via smem staging.
// ---------------------------------------------------------------------------
__global__ __launch_bounds__(512)
void gru_seq_kernel(const float* __restrict__ Whh,   // [3H, H] row-major
                    const float* __restrict__ bhh,   // [3H]
                    const float* __restrict__ gi,    // [S][3H][B]
                    float* __restrict__ hbuf,        // 2*HB ping-pong (buf0 zeroed)
                    float* __restrict__ y_out)       // [B][S][H]
{
    extern __shared__ float smem[];
    float* sw   = smem;                        // [24][1024]   96 KB
    float* sred = smem + 24 * HDIM;            // [16][24][32] 48 KB
    float* sy   = sred + 16 * 24 * 32;         // [8][32]       1 KB

    const int tid  = threadIdx.x;
    const int lane = tid & 31;                 // batch b
    const int w    = tid >> 5;                 // warp 0..15
    const int bx   = blockIdx.x;

    // Load this CTA's 24 W_hh rows into smem (once for the whole sequence).
    for (int i = tid; i < 24 * (HDIM / 4); i += 512) {
        const int r  = i >> 8;                 // row 0..23
        const int c4 = (i & 255) * 4;
        const int g = r >> 3, hl = r & 7;
        *(float4*)&sw[(size_t)r * HDIM + c4] =
            *(const float4*)&Whh[((size_t)g * HDIM + bx * 8 + hl) * HDIM + c4];
    }
    __syncthreads();

    const int hidx_f = bx * 8 + w;                 // valid for w<8
    const int pk_f   = ((hidx_f >> 2) * 32 + lane) * 4 + (hidx_f & 3);
    float bias_r = 0.f, bias_z = 0.f, bias_n = 0.f;
    if (w < 8) {
        bias_r = bhh[hidx_f];
        bias_z = bhh[HDIM + hidx_f];
        bias_n = bhh[2 * HDIM + hidx_f];
    }

    int cur = 0;
    for (int t = 0; t < SSEQ; ++t) {
        const float* h_in  = hbuf + (size_t)cur * HB;
        float*       h_out = hbuf + (size_t)(1 - cur) * HB;
        const ulonglong2* __restrict__ h2 = (const ulonglong2*)h_in;

        // --- early loads: gi[t] + h_prev (consumed after the reduction sync,
        //     ~6K cycles later — DRAM latency fully hidden) ---
        float ir = 0.f, iz = 0.f, inn = 0.f, hprev = 0.f;
        if (w < 8) {
            const float* git = gi + (size_t)t * G3H * BSZ;
            ir    = git[(size_t)hidx_f * BSZ + lane];
            iz    = git[(size_t)(HDIM + hidx_f) * BSZ + lane];
            inn   = git[(size_t)(2 * HDIM + hidx_f) * BSZ + lane];
            hprev = h_in[pk_f];
        }

        unsigned long long acc[24];
#pragma unroll
        for (int r = 0; r < 24; ++r) acc[r] = 0ull;

        const int kq0 = w * 16;
        ulonglong2 hv = h2[kq0 * 32 + lane];           // prefetch
#pragma unroll 2
        for (int kq = kq0; kq < kq0 + 16; ++kq) {
            const ulonglong2 hc = hv;
            if (kq + 1 < kq0 + 16) hv = h2[(kq + 1) * 32 + lane];
            const float* wp = sw + 4 * kq;
#pragma unroll
            for (int r = 0; r < 24; ++r) {
                const ulonglong2 wv = *(const ulonglong2*)(wp + (size_t)r * HDIM);
                fma2(acc[r], wv.x, hc.x);
                fma2(acc[r], wv.y, hc.y);
            }
        }
#pragma unroll
        for (int r = 0; r < 24; ++r) {
            const float2 f = unpack2(acc[r]);
            sred[((size_t)w * 24 + r) * 32 + lane] = f.x + f.y;
        }
        __syncthreads();

        // ---- finalize: thread (hl=w<8, b=lane) produces h[hidx_f][b] ----
        if (w < 8) {
            float gr = bias_r, gz = bias_z, gn = bias_n;
#pragma unroll
            for (int ww = 0; ww < 16; ++ww) {
                gr += sred[((size_t)ww * 24 + 0 * 8 + w) * 32 + lane];
                gz += sred[((size_t)ww * 24 + 1 * 8 + w) * 32 + lane];
                gn += sred[((size_t)ww * 24 + 2 * 8 + w) * 32 + lane];
            }
            const float r_ = 1.0f / (1.0f + expf(-(ir + gr)));
            const float z_ = 1.0f / (1.0f + expf(-(iz + gz)));
            const float n_ = tanhf(inn + r_ * gn);
            const float hn = (1.0f - z_) * n_ + z_ * hprev;

            h_out[pk_f] = hn;
            sy[w * 32 + lane] = hn;
        }
        __syncthreads();            // h_out + sy visible to whole CTA

        // coalesced y write: warp 8, lane = batch, 32B contiguous per lane
        if (w == 8) {
            float4 v0, v1;
            v0.x = sy[0 * 32 + lane]; v0.y = sy[1 * 32 + lane];
            v0.z = sy[2 * 32 + lane]; v0.w = sy[3 * 32 + lane];
            v1.x = sy[4 * 32 + lane]; v1.y = sy[5 * 32 + lane];
            v1.z = sy[6 * 32 + lane]; v1.w = sy[7 * 32 + lane];
            float* yp = y_out + ((size_t)lane * SSEQ + t) * HDIM + bx * 8;
            *(float4*)yp       = v0;
            *(float4*)(yp + 4) = v1;
        }

        // ---- grid barrier (release/acquire on monotonic counter) ----
        if (t != SSEQ - 1) {
            if (tid == 0) {
                const unsigned tgt = (unsigned)(t + 1) * RCTAS;
                unsigned* bar = &g_rbar;
                asm volatile("red.release.gpu.add.u32 [%0], %1;"
                             :: "l"(bar), "r"(1u) : "memory");
                unsigned v;
                for (;;) {
                    asm volatile("ld.acquire.gpu.u32 %0, [%1];"
                                 : "=r"(v) : "l"(bar) : "memory");
                    if (v >= tgt) break;
                    __nanosleep(32);
                }
            }
            __syncthreads();
        }
        cur ^= 1;
    }
}

// ---------------------------------------------------------------------------
__global__ void zero_h_kernel(float* __restrict__ h)
{
    const int i = blockIdx.x * 256 + threadIdx.x;
    if (i < HB) h[i] = 0.0f;
    if (i == 0) g_rbar = 0u;        // reset barrier counter (deterministic replays)
}

// h_n[0] = y0[:, S-1, :], h_n[1] = y1[:, S-1, :]
__global__ void copy_hn_kernel(const float* __restrict__ y0,
                               const float* __restrict__ y1,
                               float* __restrict__ outhn)
{
    const int i = blockIdx.x * 256 + threadIdx.x;   // 0 .. 2*B*H-1
    if (i >= 2 * HB) return;
    const int half = HB;
    if (i < half) {
        const int b = i >> 10, h = i & 1023;
        outhn[i] = y0[((size_t)b * SSEQ + (SSEQ - 1)) * HDIM + h];
    } else {
        const int j = i - half;
        const int b = j >> 10, h = j & 1023;
        outhn[i] = y1[((size_t)b * SSEQ + (SSEQ - 1)) * HDIM + h];
    }
}

// ---------------------------------------------------------------------------
extern "C" void kernel_launch(void* const* d_in, const int* in_sizes, int n_in,
                              void* d_out, int out_size)
{
    const float* x    = (const float*)d_in[0];
    const float* Wih0 = (const float*)d_in[1];
    const float* bih0 = (const float*)d_in[2];
    const float* Whh0 = (const float*)d_in[3];
    const float* bhh0 = (const float*)d_in[4];
    const float* Wih1 = (const float*)d_in[5];
    const float* bih1 = (const float*)d_in[6];
    const float* Whh1 = (const float*)d_in[7];
    const float* bhh1 = (const float*)d_in[8];
    float* out = (float*)d_out;

    float* gi;  cudaGetSymbolAddress((void**)&gi,  g_gi);
    float* y0;  cudaGetSymbolAddress((void**)&y0,  g_y0);
    float* hb;  cudaGetSymbolAddress((void**)&hb,  g_h);

    const int SMEM_REC = (24 * HDIM + 16 * 24 * 32 + 8 * 32) * (int)sizeof(float); // 148480
    static int smem_set = 0;
    if (!smem_set) {
        cudaFuncSetAttribute(gru_seq_kernel,
                             cudaFuncAttributeMaxDynamicSharedMemorySize, SMEM_REC);
        smem_set = 1;
    }

    const dim3 gemm_grid(G3H / BN, MROWS / BM);   // (24, 128)

    // ---- Layer 0 ----
    gemm_gi_kernel<<<gemm_grid, 256>>>(x, Wih0, bih0, gi);
    zero_h_kernel<<<(HB + 255) / 256, 256>>>(hb);
    gru_seq_kernel<<<RCTAS, 512, SMEM_REC>>>(Whh0, bhh0, gi, hb, y0);

    // ---- Layer 1 ----
    gemm_gi_kernel<<<gemm_grid, 256>>>(y0, Wih1, bih1, gi);
    zero_h_kernel<<<(HB + 255) / 256, 256>>>(hb);
    gru_seq_kernel<<<RCTAS, 512, SMEM_REC>>>(Whh1, bhh1, gi, hb, out);

    // ---- h_n tail (only if the harness output includes it) ----
    const long long need = (long long)MROWS * HDIM + 2LL * HB;
    if ((long long)out_size >= need) {
        copy_hn_kernel<<<(2 * HB + 255) / 256, 256>>>(y0, out, out + (size_t)MROWS * HDIM);
    }
}

// round 14
// speedup vs baseline: 1.3466x; 1.0329x over previous
#include <cuda_runtime.h>
#include <math.h>
#include <stdint.h>

// Problem constants
#define BSZ   32
#define SSEQ  512
#define HDIM  1024
#define G3H   3072                  // 3*H
#define MROWS (BSZ * SSEQ)          // 16384
#define HB    (BSZ * HDIM)          // 32768 floats per h buffer
#define RCTAS 128                   // persistent recurrent CTAs (<=148 SMs)

// ---------------------------------------------------------------------------
// Scratch (static device globals — no allocation at kernel_launch time)
// ---------------------------------------------------------------------------
__device__ float g_gi[(size_t)SSEQ * G3H * BSZ];     // [t][j][b]  192 MB
__device__ float g_y0[(size_t)MROWS * HDIM];         // [b][s][h]   64 MB
// ping-pong hidden state, lane-packed: (hidx,b) at ((hidx>>2)*32+b)*4+(hidx&3)
__device__ __align__(16) float g_h[2][HB];
__device__ unsigned g_rbar;                          // grid-barrier counter

// ---------------------------------------------------------------------------
// f32x2 packed-FMA helpers (FFMA2 — exact fp32, 2x throughput)
// ---------------------------------------------------------------------------
__device__ __forceinline__ void fma2(unsigned long long& d,
                                     unsigned long long a,
                                     unsigned long long b)
{
    asm("fma.rn.f32x2 %0, %1, %2, %3;" : "=l"(d) : "l"(a), "l"(b), "l"(d));
}
__device__ __forceinline__ unsigned long long pack2(float x)
{
    unsigned long long r;
    asm("mov.b64 %0, {%1, %1};" : "=l"(r) : "f"(x));
    return r;
}
__device__ __forceinline__ float2 unpack2(unsigned long long v)
{
    float2 f;
    asm("mov.b64 {%0, %1}, %2;" : "=f"(f.x), "=f"(f.y) : "l"(v));
    return f;
}
// L1-bypassing loads (fresh data across the grid barrier; keep L1 clean)
__device__ __forceinline__ ulonglong2 ldcg_u64x2(const ulonglong2* p)
{
    ulonglong2 v;
    asm volatile("ld.global.cg.v2.u64 {%0,%1}, [%2];"
                 : "=l"(v.x), "=l"(v.y) : "l"(p));
    return v;
}
__device__ __forceinline__ float ldcg_f32(const float* p)
{
    float v;
    asm volatile("ld.global.cg.f32 %0, [%1];" : "=f"(v) : "l"(p));
    return v;
}

// ---------------------------------------------------------------------------
// GEMM: C[m][n] = sum_k A[m][k] * W[n][k] + bias[n]
// A row-major [16384,1024], W row-major [3072,1024]
// Double-buffered smem; B stored in SPLIT-HALF layout so each microtile
// LDS.128 spans only 256B across the warp (2 wavefronts, not 4):
//   physical index of n-local j:  ((j&4)<<4) + ((j>>3)<<2) + (j&3)
// Epilogue scatters into gi[s][n][b], m = b*512 + s
// ---------------------------------------------------------------------------
#define BM 128
#define BN 128
#define BK 16
#define TM 8
#define TN 8

__device__ __forceinline__ int bperm(int j)
{
    return ((j & 4) << 4) + ((j >> 3) << 2) + (j & 3);
}

__global__ __launch_bounds__(256, 2)
void gemm_gi_kernel(const float* __restrict__ A,
                    const float* __restrict__ W,
                    const float* __restrict__ bias,
                    float* __restrict__ gi)
{
    __shared__ float As[2][BK][BM];   // 16 KB
    __shared__ float Bs[2][BK][BN];   // 16 KB (split-half permuted layout)

    const int tid = threadIdx.x;
    const int tx = tid & 15;          // n microtile
    const int ty = tid >> 4;          // m microtile
    const int m0 = blockIdx.y * BM;
    const int n0 = blockIdx.x * BN;

    const int lrow = tid >> 2;            // 0..63
    const int lc4  = (tid & 3) * 4;       // 0,4,8,12
    const int bp0  = bperm(lrow);
    const int bp1  = bperm(lrow + 64);

    const float* Ab = A + (size_t)(m0 + lrow) * HDIM + lc4;
    const float* Wb = W + (size_t)(n0 + lrow) * HDIM + lc4;

    float4 pa0 = *(const float4*)(Ab);
    float4 pa1 = *(const float4*)(Ab + (size_t)64 * HDIM);
    float4 pb0 = *(const float4*)(Wb);
    float4 pb1 = *(const float4*)(Wb + (size_t)64 * HDIM);

    unsigned long long acc2[TM][TN / 2];
#pragma unroll
    for (int i = 0; i < TM; i++)
#pragma unroll
        for (int j = 0; j < TN / 2; j++) acc2[i][j] = 0ull;

    // stage tile 0 into buffer 0
    {
        As[0][lc4 + 0][lrow] = pa0.x; As[0][lc4 + 1][lrow] = pa0.y;
        As[0][lc4 + 2][lrow] = pa0.z; As[0][lc4 + 3][lrow] = pa0.w;
        As[0][lc4 + 0][lrow + 64] = pa1.x; As[0][lc4 + 1][lrow + 64] = pa1.y;
        As[0][lc4 + 2][lrow + 64] = pa1.z; As[0][lc4 + 3][lrow + 64] = pa1.w;
        Bs[0][lc4 + 0][bp0] = pb0.x; Bs[0][lc4 + 1][bp0] = pb0.y;
        Bs[0][lc4 + 2][bp0] = pb0.z; Bs[0][lc4 + 3][bp0] = pb0.w;
        Bs[0][lc4 + 0][bp1] = pb1.x; Bs[0][lc4 + 1][bp1] = pb1.y;
        Bs[0][lc4 + 2][bp1] = pb1.z; Bs[0][lc4 + 3][bp1] = pb1.w;
    }
    __syncthreads();

    int buf = 0;
    for (int k0 = 0; k0 < HDIM; k0 += BK) {
        const bool nxt = (k0 + BK < HDIM);
        if (nxt) {
            pa0 = *(const float4*)(Ab + k0 + BK);
            pa1 = *(const float4*)(Ab + (size_t)64 * HDIM + k0 + BK);
            pb0 = *(const float4*)(Wb + k0 + BK);
            pb1 = *(const float4*)(Wb + (size_t)64 * HDIM + k0 + BK);
        }

#pragma unroll
        for (int kk = 0; kk < BK; kk++) {
            float4 a0 = *(const float4*)&As[buf][kk][ty * TM];
            float4 a1 = *(const float4*)&As[buf][kk][ty * TM + 4];
            // split-half: lanes span 256B per request (2 wavefronts)
            ulonglong2 bl0 = *(const ulonglong2*)&Bs[buf][kk][tx * 4];       // n pairs (0,1),(2,3)
            ulonglong2 bl1 = *(const ulonglong2*)&Bs[buf][kk][64 + tx * 4];  // n pairs (4,5),(6,7)
            float ar[TM] = {a0.x, a0.y, a0.z, a0.w, a1.x, a1.y, a1.z, a1.w};
#pragma unroll
            for (int i = 0; i < TM; i++) {
                const unsigned long long aa = pack2(ar[i]);
                fma2(acc2[i][0], aa, bl0.x);
                fma2(acc2[i][1], aa, bl0.y);
                fma2(acc2[i][2], aa, bl1.x);
                fma2(acc2[i][3], aa, bl1.y);
            }
        }

        if (nxt) {
            const int nb = buf ^ 1;
            As[nb][lc4 + 0][lrow] = pa0.x; As[nb][lc4 + 1][lrow] = pa0.y;
            As[nb][lc4 + 2][lrow] = pa0.z; As[nb][lc4 + 3][lrow] = pa0.w;
            As[nb][lc4 + 0][lrow + 64] = pa1.x; As[nb][lc4 + 1][lrow + 64] = pa1.y;
            As[nb][lc4 + 2][lrow + 64] = pa1.z; As[nb][lc4 + 3][lrow + 64] = pa1.w;
            Bs[nb][lc4 + 0][bp0] = pb0.x; Bs[nb][lc4 + 1][bp0] = pb0.y;
            Bs[nb][lc4 + 2][bp0] = pb0.z; Bs[nb][lc4 + 3][bp0] = pb0.w;
            Bs[nb][lc4 + 0][bp1] = pb1.x; Bs[nb][lc4 + 1][bp1] = pb1.y;
            Bs[nb][lc4 + 2][bp1] = pb1.z; Bs[nb][lc4 + 3][bp1] = pb1.w;
            __syncthreads();
            buf = nb;
        }
    }

    // Epilogue: add bias, scatter to gi[t][j][b]
#pragma unroll
    for (int i = 0; i < TM; i++) {
        const int m = m0 + ty * TM + i;
        const int b = m >> 9;           // m / 512
        const int s = m & 511;          // m % 512
#pragma unroll
        for (int j2 = 0; j2 < TN / 2; j2++) {
            const float2 v = unpack2(acc2[i][j2]);
            const int n = n0 + tx * TN + 2 * j2;
            gi[((size_t)s * G3H + n) * BSZ + b]     = v.x + bias[n];
            gi[((size_t)s * G3H + n + 1) * BSZ + b] = v.y + bias[n + 1];
        }
    }
}

// ---------------------------------------------------------------------------
// Persistent GRU recurrence: whole sequence in ONE launch.
// 128 CTAs x 512 threads (16 warps). CTA owns 8 hidden units (24 gate rows).
// W_hh slice (96 KB) resident in smem for the entire sequence.
// Per step: warp w loads its 64-float h-chunk into REGISTERS once, then
// iterates row-PAIRS with 4 accumulator chains (low register pressure, no
// spills). Cross-warp k-reduction via smem; coalesced y write via staging.
// ---------------------------------------------------------------------------
__global__ __launch_bounds__(512)
void gru_seq_kernel(const float* __restrict__ Whh,   // [3H, H] row-major
                    const float* __restrict__ bhh,   // [3H]
                    const float* __restrict__ gi,    // [S][3H][B]
                    float* __restrict__ hbuf,        // 2*HB ping-pong (buf0 zeroed)
                    float* __restrict__ y_out)       // [B][S][H]
{
    extern __shared__ float smem[];
    float* sw   = smem;                        // [24][1024]   96 KB
    float* sred = smem + 24 * HDIM;            // [16][24][32] 48 KB
    float* sy   = sred + 16 * 24 * 32;         // [8][32]       1 KB

    const int tid  = threadIdx.x;
    const int lane = tid & 31;                 // batch b
    const int w    = tid >> 5;                 // warp 0..15
    const int bx   = blockIdx.x;

    // Load this CTA's 24 W_hh rows into smem (once for the whole sequence).
    for (int i = tid; i < 24 * (HDIM / 4); i += 512) {
        const int r  = i >> 8;                 // row 0..23
        const int c4 = (i & 255) * 4;
        const int g = r >> 3, hl = r & 7;
        *(float4*)&sw[(size_t)r * HDIM + c4] =
            *(const float4*)&Whh[((size_t)g * HDIM + bx * 8 + hl) * HDIM + c4];
    }
    __syncthreads();

    const int hidx_f = bx * 8 + w;                 // valid for w<8
    const int pk_f   = ((hidx_f >> 2) * 32 + lane) * 4 + (hidx_f & 3);
    float bias_r = 0.f, bias_z = 0.f, bias_n = 0.f;
    if (w < 8) {
        bias_r = bhh[hidx_f];
        bias_z = bhh[HDIM + hidx_f];
        bias_n = bhh[2 * HDIM + hidx_f];
    }

    const int kq0 = w * 16;

    int cur = 0;
    for (int t = 0; t < SSEQ; ++t) {
        const float* h_in  = hbuf + (size_t)cur * HB;
        float*       h_out = hbuf + (size_t)(1 - cur) * HB;
        const ulonglong2* __restrict__ h2 = (const ulonglong2*)h_in;

        // --- early loads: gi[t] + h_prev (consumed after reduction sync) ---
        float ir = 0.f, iz = 0.f, inn = 0.f, hprev = 0.f;
        if (w < 8) {
            const float* git = gi + (size_t)t * G3H * BSZ;
            ir    = ldcg_f32(&git[(size_t)hidx_f * BSZ + lane]);
            iz    = ldcg_f32(&git[(size_t)(HDIM + hidx_f) * BSZ + lane]);
            inn   = ldcg_f32(&git[(size_t)(2 * HDIM + hidx_f) * BSZ + lane]);
            hprev = ldcg_f32(&h_in[pk_f]);
        }

        // --- load warp's h chunk (64 floats) into registers, L1-bypassing ---
        ulonglong2 hreg[16];
#pragma unroll
        for (int i = 0; i < 16; ++i)
            hreg[i] = ldcg_u64x2(&h2[(kq0 + i) * 32 + lane]);

        // --- row-pair loop: 2 rows x 2 packed chains = 4 live accumulators ---
        const float* wbase = sw + 4 * kq0;
#pragma unroll 2
        for (int rp = 0; rp < 12; ++rp) {
            const float* wp0 = wbase + (size_t)(2 * rp) * HDIM;
            const float* wp1 = wp0 + HDIM;
            unsigned long long a0 = 0ull, a1 = 0ull, b0 = 0ull, b1 = 0ull;
#pragma unroll
            for (int i = 0; i < 16; ++i) {
                const ulonglong2 w0 = *(const ulonglong2*)(wp0 + 4 * i);
                const ulonglong2 w1 = *(const ulonglong2*)(wp1 + 4 * i);
                fma2(a0, w0.x, hreg[i].x);
                fma2(a1, w0.y, hreg[i].y);
                fma2(b0, w1.x, hreg[i].x);
                fma2(b1, w1.y, hreg[i].y);
            }
            const float2 fa0 = unpack2(a0), fa1 = unpack2(a1);
            const float2 fb0 = unpack2(b0), fb1 = unpack2(b1);
            sred[((size_t)w * 24 + 2 * rp) * 32 + lane]     = (fa0.x + fa0.y) + (fa1.x + fa1.y);
            sred[((size_t)w * 24 + 2 * rp + 1) * 32 + lane] = (fb0.x + fb0.y) + (fb1.x + fb1.y);
        }
        __syncthreads();

        // ---- finalize: thread (hl=w<8, b=lane) produces h[hidx_f][b] ----
        if (w < 8) {
            float gr = bias_r, gz = bias_z, gn = bias_n;
#pragma unroll
            for (int ww = 0; ww < 16; ++ww) {
                gr += sred[((size_t)ww * 24 + 0 * 8 + w) * 32 + lane];
                gz += sred[((size_t)ww * 24 + 1 * 8 + w) * 32 + lane];
                gn += sred[((size_t)ww * 24 + 2 * 8 + w) * 32 + lane];
            }
            const float r_ = 1.0f / (1.0f + expf(-(ir + gr)));
            const float z_ = 1.0f / (1.0f + expf(-(iz + gz)));
            const float n_ = tanhf(inn + r_ * gn);
            const float hn = (1.0f - z_) * n_ + z_ * hprev;

            h_out[pk_f] = hn;
            sy[w * 32 + lane] = hn;
        }
        __syncthreads();            // h_out + sy visible to whole CTA

        // coalesced y write: warp 8 (overlaps the barrier poll below)
        if (w == 8) {
            float4 v0, v1;
            v0.x = sy[0 * 32 + lane]; v0.y = sy[1 * 32 + lane];
            v0.z = sy[2 * 32 + lane]; v0.w = sy[3 * 32 + lane];
            v1.x = sy[4 * 32 + lane]; v1.y = sy[5 * 32 + lane];
            v1.z = sy[6 * 32 + lane]; v1.w = sy[7 * 32 + lane];
            float* yp = y_out + ((size_t)lane * SSEQ + t) * HDIM + bx * 8;
            *(float4*)yp       = v0;
            *(float4*)(yp + 4) = v1;
        }

        // ---- grid barrier (release/acquire on monotonic counter) ----
        if (t != SSEQ - 1) {
            if (tid == 0) {
                const unsigned tgt = (unsigned)(t + 1) * RCTAS;
                unsigned* bar = &g_rbar;
                asm volatile("red.release.gpu.add.u32 [%0], %1;"
                             :: "l"(bar), "r"(1u) : "memory");
                unsigned v;
                for (;;) {
                    asm volatile("ld.acquire.gpu.u32 %0, [%1];"
                                 : "=r"(v) : "l"(bar) : "memory");
                    if (v >= tgt) break;
                    __nanosleep(16);
                }
            }
            __syncthreads();
        }
        cur ^= 1;
    }
}

// ---------------------------------------------------------------------------
__global__ void zero_h_kernel(float* __restrict__ h)
{
    const int i = blockIdx.x * 256 + threadIdx.x;
    if (i < HB) h[i] = 0.0f;
    if (i == 0) g_rbar = 0u;        // reset barrier counter (deterministic replays)
}

// h_n[0] = y0[:, S-1, :], h_n[1] = y1[:, S-1, :]
__global__ void copy_hn_kernel(const float* __restrict__ y0,
                               const float* __restrict__ y1,
                               float* __restrict__ outhn)
{
    const int i = blockIdx.x * 256 + threadIdx.x;   // 0 .. 2*B*H-1
    if (i >= 2 * HB) return;
    const int half = HB;
    if (i < half) {
        const int b = i >> 10, h = i & 1023;
        outhn[i] = y0[((size_t)b * SSEQ + (SSEQ - 1)) * HDIM + h];
    } else {
        const int j = i - half;
        const int b = j >> 10, h = j & 1023;
        outhn[i] = y1[((size_t)b * SSEQ + (SSEQ - 1)) * HDIM + h];
    }
}

// ---------------------------------------------------------------------------
extern "C" void kernel_launch(void* const* d_in, const int* in_sizes, int n_in,
                              void* d_out, int out_size)
{
    const float* x    = (const float*)d_in[0];
    const float* Wih0 = (const float*)d_in[1];
    const float* bih0 = (const float*)d_in[2];
    const float* Whh0 = (const float*)d_in[3];
    const float* bhh0 = (const float*)d_in[4];
    const float* Wih1 = (const float*)d_in[5];
    const float* bih1 = (const float*)d_in[6];
    const float* Whh1 = (const float*)d_in[7];
    const float* bhh1 = (const float*)d_in[8];
    float* out = (float*)d_out;

    float* gi;  cudaGetSymbolAddress((void**)&gi,  g_gi);
    float* y0;  cudaGetSymbolAddress((void**)&y0,  g_y0);
    float* hb;  cudaGetSymbolAddress((void**)&hb,  g_h);

    const int SMEM_REC = (24 * HDIM + 16 * 24 * 32 + 8 * 32) * (int)sizeof(float); // 148480
    static int smem_set = 0;
    if (!smem_set) {
        cudaFuncSetAttribute(gru_seq_kernel,
                             cudaFuncAttributeMaxDynamicSharedMemorySize, SMEM_REC);
        smem_set = 1;
    }

    const dim3 gemm_grid(G3H / BN, MROWS / BM);   // (24, 128)

    // ---- Layer 0 ----
    gemm_gi_kernel<<<gemm_grid, 256>>>(x, Wih0, bih0, gi);
    zero_h_kernel<<<(HB + 255) / 256, 256>>>(hb);
    gru_seq_kernel<<<RCTAS, 512, SMEM_REC>>>(Whh0, bhh0, gi, hb, y0);

    // ---- Layer 1 ----
    gemm_gi_kernel<<<gemm_grid, 256>>>(y0, Wih1, bih1, gi);
    zero_h_kernel<<<(HB + 255) / 256, 256>>>(hb);
    gru_seq_kernel<<<RCTAS, 512, SMEM_REC>>>(Whh1, bhh1, gi, hb, out);

    // ---- h_n tail (only if the harness output includes it) ----
    const long long need = (long long)MROWS * HDIM + 2LL * HB;
    if ((long long)out_size >= need) {
        copy_hn_kernel<<<(2 * HB + 255) / 256, 256>>>(y0, out, out + (size_t)MROWS * HDIM);
    }
}